// round 12
// baseline (speedup 1.0000x reference)
#include <cuda_runtime.h>
#include <cuda_fp16.h>
#include <cstdint>

// Problem dims (fixed by setup_inputs)
#define BB 128
#define TT 512
#define DD 256
#define HH 512
#define BH (BB*HH)        // 65536
#define TBH (TT*BH)       // 33554432 per projection
#define MM (BB*TT)        // 65536 GEMM rows

// ---------------------------------------------------------------------------
// Static device scratch (allocation-free per harness rules)
// Scratch layout: [w][t][b][h] fp16 (contiguous h).
// ---------------------------------------------------------------------------
__device__ __half g_scratch[3u * TBH];                 // 201 MB
__device__ __half g_bsplit[3u * 512 * 256];            // 0.75 MB: [w][n=h][k=d] fp16

__device__ __forceinline__ uint32_t smem_u32(const void* p) {
    uint32_t a;
    asm("{ .reg .u64 t; cvta.to.shared.u64 t, %1; cvt.u32.u64 %0, t; }" : "=r"(a) : "l"(p));
    return a;
}

__device__ __forceinline__ float htanh(float x) {
    float y;
    asm("tanh.approx.f32 %0, %1;" : "=f"(y) : "f"(x));
    return y;
}

#define CP_ASYNC_16(smem, gmem) \
    asm volatile("cp.async.cg.shared.global [%0], [%1], 16;" :: "r"(smem), "l"(gmem))
#define CP_ASYNC_COMMIT() asm volatile("cp.async.commit_group;")
#define CP_ASYNC_WAIT_2() asm volatile("cp.async.wait_group 2;")

// ---------------------------------------------------------------------------
// Kernel 0: weights -> fp16 transposed [w][n=h][k=d]
// ---------------------------------------------------------------------------
__global__ __launch_bounds__(256)
void convert_w(const float* __restrict__ wr,
               const float* __restrict__ wz,
               const float* __restrict__ wh)
{
    int i = blockIdx.x * 256 + threadIdx.x;        // total 3*256*512
    int w = i / (DD * HH);
    int rem = i - w * (DD * HH);
    int d = rem >> 9;
    int h = rem & 511;
    const float* W = (w == 0) ? wr : ((w == 1) ? wz : wh);
    g_bsplit[((size_t)w * 512 + h) * 256 + d] = __float2half_rn(W[d * HH + h]);
}

// ---------------------------------------------------------------------------
// Kernel 1: A-resident mma.sync fp16 GEMM (at legacy-HMMA floor).
// Parameterized by m-tile offset my0 so the launch can be split into
// b-quarters for stream-level overlap with the scan.
// grid = (4 n-groups, 128 m-tiles per quarter), 256 threads (8 warps: 2m x 4n).
// ---------------------------------------------------------------------------
#define APITCH 264
#define BPITCH 40
#define NSTAGE 4
#define BTILE_ELT (128 * BPITCH)
#define A_BYTES (128 * APITCH * 2)                  // 67584
#define GEMM_SMEM (A_BYTES + NSTAGE * BTILE_ELT * 2) // 108544
#define NQ 24                                        // 3 n-blocks * 8 chunks

__global__ __launch_bounds__(256, 2)
void gemm_mma(const float* __restrict__ x,
              const float* __restrict__ br,
              const float* __restrict__ bz,
              int my0)
{
    extern __shared__ __align__(16) __half sm[];
    __half* At  = sm;                                // [128][APITCH]
    __half* Brg = sm + 128 * APITCH;                 // ring: 4 x [128][BPITCH]

    const int tid  = threadIdx.x;
    const int wid  = tid >> 5;
    const int lane = tid & 31;
    const int warp_m = wid >> 2;       // 0..1
    const int warp_n = wid & 3;        // 0..3

    const int bx = blockIdx.x;         // n-group 0..3 -> nt = bx*3 + (0..2)
    const int m0 = (my0 + blockIdx.y) * 128;

    float acc[4][4][4];
#pragma unroll
    for (int i = 0; i < 4; i++)
#pragma unroll
        for (int j = 0; j < 4; j++)
#pragma unroll
            for (int q = 0; q < 4; q++) acc[i][j][q] = 0.0f;

    auto load_chunk = [&](int q) {
        if (q < NQ) {
            const int nt = bx * 3 + (q >> 3);
            const int k0 = (q & 7) * 32;
            const __half* gB = g_bsplit
                + (((size_t)(nt >> 2) * 512) + (nt & 3) * 128) * 256;
            __half* Bs = Brg + (q & (NSTAGE - 1)) * BTILE_ELT;
#pragma unroll
            for (int it = 0; it < 2; it++) {
                int idx = tid + it * 256;
                int r = idx >> 2, cc = (idx & 3) * 8;
                CP_ASYNC_16(smem_u32(Bs + r * BPITCH + cc),
                            gB + (size_t)r * 256 + k0 + cc);
            }
        }
        CP_ASYNC_COMMIT();
    };

    load_chunk(0);
    load_chunk(1);
    load_chunk(2);

    // A: 128 rows x 256 fp32 -> fp16, 8192 float4, 32 per thread.
    {
        const float4* xs = (const float4*)(x + (size_t)m0 * 256);
#pragma unroll 8
        for (int it = 0; it < 32; it++) {
            int idx = tid + it * 256;
            int r = idx >> 6;
            int c4 = (idx & 63) * 4;
            float4 v = __ldg(xs + (size_t)r * 64 + (idx & 63));
            union { __half b[4]; uint2 u; } H;
            H.b[0] = __float2half_rn(v.x);
            H.b[1] = __float2half_rn(v.y);
            H.b[2] = __float2half_rn(v.z);
            H.b[3] = __float2half_rn(v.w);
            *(uint2*)(At + r * APITCH + c4) = H.u;
        }
    }

    const int a_row_sel = warp_m * 64 + (lane & 15);
    const int a_col_sel = (lane & 16) ? 8 : 0;
    const int b_row_sel = warp_n * 32 + (lane & 7);
    const int b_col_sel = (lane & 8) ? 8 : 0;

    for (int q = 0; q < NQ; q++) {
        const int st = q & (NSTAGE - 1);
        CP_ASYNC_WAIT_2();
        __syncthreads();
        load_chunk(q + 3);

        const int k0 = (q & 7) * 32;
        const __half* Bs = Brg + st * BTILE_ELT;

#pragma unroll
        for (int kk = 0; kk < 2; kk++) {
            uint32_t afrag[4][4];
            uint32_t bfrag[4][2];
#pragma unroll
            for (int ni = 0; ni < 4; ni++) {
                uint32_t addr = smem_u32(Bs + (b_row_sel + ni * 8) * BPITCH + kk * 16 + b_col_sel);
                asm volatile("ldmatrix.sync.aligned.m8n8.x2.shared.b16 {%0,%1}, [%2];"
                    : "=r"(bfrag[ni][0]), "=r"(bfrag[ni][1])
                    : "r"(addr));
            }
#pragma unroll
            for (int mi = 0; mi < 4; mi++) {
                uint32_t addr = smem_u32(At + (a_row_sel + mi * 16) * APITCH + k0 + kk * 16 + a_col_sel);
                asm volatile("ldmatrix.sync.aligned.m8n8.x4.shared.b16 {%0,%1,%2,%3}, [%4];"
                    : "=r"(afrag[mi][0]), "=r"(afrag[mi][1]), "=r"(afrag[mi][2]), "=r"(afrag[mi][3])
                    : "r"(addr));
            }
#pragma unroll
            for (int mi = 0; mi < 4; mi++) {
#pragma unroll
                for (int ni = 0; ni < 4; ni++) {
                    asm volatile(
                        "mma.sync.aligned.m16n8k16.row.col.f32.f16.f16.f32 "
                        "{%0,%1,%2,%3}, {%4,%5,%6,%7}, {%8,%9}, {%0,%1,%2,%3};"
                        : "+f"(acc[mi][ni][0]), "+f"(acc[mi][ni][1]),
                          "+f"(acc[mi][ni][2]), "+f"(acc[mi][ni][3])
                        : "r"(afrag[mi][0]), "r"(afrag[mi][1]), "r"(afrag[mi][2]), "r"(afrag[mi][3]),
                          "r"(bfrag[ni][0]), "r"(bfrag[ni][1]));
                }
            }
        }

        // End of an n-block: epilogue (contiguous half2) + acc reset
        if ((q & 7) == 7) {
            const int nt    = bx * 3 + (q >> 3);
            const int w_idx = nt >> 2;
            const int nbase = (nt & 3) * 128;
            const int g  = lane >> 2;
            const int tg = lane & 3;

            const float* bsrc = (w_idx == 0) ? br : ((w_idx == 1) ? bz : nullptr);
            float2 bias[4];
#pragma unroll
            for (int ni = 0; ni < 4; ni++) {
                int hh = nbase + warp_n * 32 + tg * 2 + ni * 8;
                bias[ni] = bsrc ? *(const float2*)(bsrc + hh) : make_float2(0.f, 0.f);
            }

#pragma unroll
            for (int mi = 0; mi < 4; mi++) {
#pragma unroll
                for (int rr = 0; rr < 2; rr++) {
                    int m  = m0 + warp_m * 64 + mi * 16 + g + rr * 8;
                    int bb = m >> 9;
                    int t  = m & 511;
                    __half* dst = g_scratch + (size_t)w_idx * TBH + (size_t)t * BH
                                + (size_t)bb * HH + nbase + warp_n * 32 + tg * 2;
#pragma unroll
                    for (int ni = 0; ni < 4; ni++) {
                        float vx = (rr ? acc[mi][ni][2] : acc[mi][ni][0]) + bias[ni].x;
                        float vy = (rr ? acc[mi][ni][3] : acc[mi][ni][1]) + bias[ni].y;
                        *(__half2*)(dst + ni * 8) = __floats2half2_rn(vx, vy);
                    }
                }
            }

#pragma unroll
            for (int i = 0; i < 4; i++)
#pragma unroll
                for (int j = 0; j < 4; j++)
#pragma unroll
                    for (int qq = 0; qq < 4; qq++) acc[i][j][qq] = 0.0f;
        }
    }
}

// ---------------------------------------------------------------------------
// Kernel 2: diagonal recurrence scan (b-quarter via idx0).
// 512-thread blocks; depth-16 ring prefetch; HW tanh.approx.
// ---------------------------------------------------------------------------
#define PFD 16

__global__ __launch_bounds__(512)
void scan_kernel(const float* __restrict__ h0,
                 const float* __restrict__ mr,
                 const float* __restrict__ mz,
                 float* __restrict__ out,
                 int idx0)
{
    const int idx = idx0 + blockIdx.x * 512 + threadIdx.x;
    const int h = idx & (HH - 1);
    const int b = idx >> 9;

    float state = h0[idx];
    const float mrv = mr[h];
    const float mzv = mz[h];

    const __half* pr = g_scratch + idx;
    const __half* pz = g_scratch + TBH + idx;
    const __half* ph = g_scratch + 2u * TBH + idx;

    float* o = out + (size_t)b * (TT * HH) + h;

    __half pa[PFD], pc[PFD], pd[PFD];
#pragma unroll
    for (int u = 0; u < PFD; u++) {
        size_t off = (size_t)u * BH;
        pa[u] = __ldg(pr + off);
        pc[u] = __ldg(pz + off);
        pd[u] = __ldg(ph + off);
    }

    for (int tb = 0; tb < TT; tb += PFD) {
#pragma unroll
        for (int u = 0; u < PFD; u++) {
            const int t = tb + u;
            float a0 = __half2float(pa[u]);
            float c0 = __half2float(pc[u]);
            float d0 = __half2float(pd[u]);

            if (t + PFD < TT) {
                size_t off = (size_t)(t + PFD) * BH;
                pa[u] = __ldg(pr + off);
                pc[u] = __ldg(pz + off);
                pd[u] = __ldg(ph + off);
            }

            float r = htanh(fmaf(state, mrv, a0)) + 1.0f;
            float z = fmaf(0.5f, htanh(0.5f * fmaf(state, mzv, c0)), 0.5f);
            float inner = htanh(fmaf(r, state, d0));
            state = fmaf(z, state - inner, inner);   // z*h + (1-z)*inner

            __stcs(o + (size_t)t * HH, state);
        }
    }
}

// ---------------------------------------------------------------------------
// Launch: 4-way b-quarter pipeline across two streams.
//   stream0: convert -> G0 -e0-> G1 -e1-> G2 -e2-> G3 -e3
//   s2:      w(e0) S0, w(e1) S1, w(e2) S2, w(e3) S3 -> eF
//   stream0: wait(eF)
// ---------------------------------------------------------------------------
#define NSPLIT 4
#define MY_PER (512 / NSPLIT)        // 128 m-tiles per quarter
#define IDX_PER (BH / NSPLIT)        // 16384 lanes per quarter

extern "C" void kernel_launch(void* const* d_in, const int* in_sizes, int n_in,
                              void* d_out, int out_size)
{
    const float* x  = (const float*)d_in[0];
    const float* h0 = (const float*)d_in[1];
    const float* wr = (const float*)d_in[2];
    const float* wz = (const float*)d_in[3];
    const float* wh = (const float*)d_in[4];
    const float* mr = (const float*)d_in[5];
    const float* mz = (const float*)d_in[6];
    const float* br = (const float*)d_in[7];
    const float* bz = (const float*)d_in[8];
    float* out = (float*)d_out;

    static cudaStream_t s2 = nullptr;
    static cudaEvent_t eg[NSPLIT], ef;
    if (!s2) {
        cudaFuncSetAttribute(gemm_mma, cudaFuncAttributeMaxDynamicSharedMemorySize, GEMM_SMEM);
        cudaStreamCreateWithFlags(&s2, cudaStreamNonBlocking);
        for (int i = 0; i < NSPLIT; i++)
            cudaEventCreateWithFlags(&eg[i], cudaEventDisableTiming);
        cudaEventCreateWithFlags(&ef, cudaEventDisableTiming);
    }

    convert_w<<<(3 * DD * HH) / 256, 256>>>(wr, wz, wh);

    for (int i = 0; i < NSPLIT; i++) {
        dim3 ggrid(4, MY_PER);
        gemm_mma<<<ggrid, 256, GEMM_SMEM>>>(x, br, bz, i * MY_PER);
        cudaEventRecord(eg[i], 0);
        cudaStreamWaitEvent(s2, eg[i], 0);
        scan_kernel<<<IDX_PER / 512, 512, 0, s2>>>(h0, mr, mz, out, i * IDX_PER);
    }
    cudaEventRecord(ef, s2);
    cudaStreamWaitEvent(0, ef, 0);
}

// round 13
// speedup vs baseline: 1.3078x; 1.3078x over previous
#include <cuda_runtime.h>
#include <cuda_fp16.h>
#include <cstdint>

// Problem dims (fixed by setup_inputs)
#define BB 128
#define TT 512
#define DD 256
#define HH 512
#define BH (BB*HH)        // 65536
#define TBH (TT*BH)       // 33554432 per projection
#define MM (BB*TT)        // 65536 GEMM rows

// ---------------------------------------------------------------------------
// Static device scratch (allocation-free per harness rules)
// Scratch layout: [w][t][b][h] fp16 (contiguous h).
// ---------------------------------------------------------------------------
__device__ __half g_scratch[3u * TBH];                 // 201 MB
__device__ __half g_bsplit[3u * 512 * 256];            // 0.75 MB: [w][n=h][k=d] fp16
__device__ int    g_flags[512];                        // per-m-tile completion count (target 4)

__device__ __forceinline__ uint32_t smem_u32(const void* p) {
    uint32_t a;
    asm("{ .reg .u64 t; cvta.to.shared.u64 t, %1; cvt.u32.u64 %0, t; }" : "=r"(a) : "l"(p));
    return a;
}

__device__ __forceinline__ float htanh(float x) {
    float y;
    asm("tanh.approx.f32 %0, %1;" : "=f"(y) : "f"(x));
    return y;
}

#define CP_ASYNC_16(smem, gmem) \
    asm volatile("cp.async.cg.shared.global [%0], [%1], 16;" :: "r"(smem), "l"(gmem))
#define CP_ASYNC_COMMIT() asm volatile("cp.async.commit_group;")
#define CP_ASYNC_WAIT_2() asm volatile("cp.async.wait_group 2;")

// ---------------------------------------------------------------------------
// Kernel 0: weights -> fp16 transposed [w][n=h][k=d]; block 0 zeroes flags.
// ---------------------------------------------------------------------------
__global__ __launch_bounds__(256)
void convert_w(const float* __restrict__ wr,
               const float* __restrict__ wz,
               const float* __restrict__ wh)
{
    if (blockIdx.x == 0) {
        g_flags[threadIdx.x]       = 0;
        g_flags[threadIdx.x + 256] = 0;
    }
    int i = blockIdx.x * 256 + threadIdx.x;        // total 3*256*512
    int w = i / (DD * HH);
    int rem = i - w * (DD * HH);
    int d = rem >> 9;
    int h = rem & 511;
    const float* W = (w == 0) ? wr : ((w == 1) ? wz : wh);
    g_bsplit[((size_t)w * 512 + h) * 256 + d] = __float2half_rn(W[d * HH + h]);
}

// ---------------------------------------------------------------------------
// Kernel 1 (fused): bids [0,2048) = GEMM role, bids [2048,2304) = scan role.
//
// GEMM role: A-resident mma.sync fp16 GEMM. m-tile = bid>>2, n-group = bid&3.
//   Signals g_flags[m-tile] (4 CTAs per m-tile) when its outputs are visible.
// Scan role: one batch b per CTA (256 threads, half the h-range each of 2 CTAs).
//   Polls flags per 128-t block, then runs the ring-prefetch recurrence.
// Deadlock-safe: 256 scan CTAs < 296 resident slots.
// ---------------------------------------------------------------------------
#define APITCH 264
#define BPITCH 40
#define NSTAGE 4
#define BTILE_ELT (128 * BPITCH)
#define A_BYTES (128 * APITCH * 2)                  // 67584
#define GEMM_SMEM (A_BYTES + NSTAGE * BTILE_ELT * 2) // 108544
#define NQ 24                                        // 3 n-blocks * 8 chunks
#define NGEMM 2048
#define NSCAN 256
#define PFD 16

__global__ __launch_bounds__(256, 2)
void fused_kernel(const float* __restrict__ x,
                  const float* __restrict__ br,
                  const float* __restrict__ bz,
                  const float* __restrict__ h0,
                  const float* __restrict__ mr,
                  const float* __restrict__ mz,
                  float* __restrict__ out)
{
    const int bid = blockIdx.x;
    const int tid = threadIdx.x;

    if (bid < NGEMM) {
        // =================== GEMM role ===================
        extern __shared__ __align__(16) __half sm[];
        __half* At  = sm;                                // [128][APITCH]
        __half* Brg = sm + 128 * APITCH;                 // ring: 4 x [128][BPITCH]

        const int wid  = tid >> 5;
        const int lane = tid & 31;
        const int warp_m = wid >> 2;       // 0..1
        const int warp_n = wid & 3;        // 0..3

        const int my = bid >> 2;           // m-tile 0..511 (completes in ~b order)
        const int bx = bid & 3;            // n-group 0..3
        const int m0 = my * 128;

        float acc[4][4][4];
#pragma unroll
        for (int i = 0; i < 4; i++)
#pragma unroll
            for (int j = 0; j < 4; j++)
#pragma unroll
                for (int q = 0; q < 4; q++) acc[i][j][q] = 0.0f;

        auto load_chunk = [&](int q) {
            if (q < NQ) {
                const int nt = bx * 3 + (q >> 3);
                const int k0 = (q & 7) * 32;
                const __half* gB = g_bsplit
                    + (((size_t)(nt >> 2) * 512) + (nt & 3) * 128) * 256;
                __half* Bs = Brg + (q & (NSTAGE - 1)) * BTILE_ELT;
#pragma unroll
                for (int it = 0; it < 2; it++) {
                    int idx = tid + it * 256;
                    int r = idx >> 2, cc = (idx & 3) * 8;
                    CP_ASYNC_16(smem_u32(Bs + r * BPITCH + cc),
                                gB + (size_t)r * 256 + k0 + cc);
                }
            }
            CP_ASYNC_COMMIT();
        };

        load_chunk(0);
        load_chunk(1);
        load_chunk(2);

        // A: 128 rows x 256 fp32 -> fp16, 8192 float4, 32 per thread.
        {
            const float4* xs = (const float4*)(x + (size_t)m0 * 256);
#pragma unroll 8
            for (int it = 0; it < 32; it++) {
                int idx = tid + it * 256;
                int r = idx >> 6;
                int c4 = (idx & 63) * 4;
                float4 v = __ldg(xs + (size_t)r * 64 + (idx & 63));
                union { __half b[4]; uint2 u; } H;
                H.b[0] = __float2half_rn(v.x);
                H.b[1] = __float2half_rn(v.y);
                H.b[2] = __float2half_rn(v.z);
                H.b[3] = __float2half_rn(v.w);
                *(uint2*)(At + r * APITCH + c4) = H.u;
            }
        }

        const int a_row_sel = warp_m * 64 + (lane & 15);
        const int a_col_sel = (lane & 16) ? 8 : 0;
        const int b_row_sel = warp_n * 32 + (lane & 7);
        const int b_col_sel = (lane & 8) ? 8 : 0;

        for (int q = 0; q < NQ; q++) {
            const int st = q & (NSTAGE - 1);
            CP_ASYNC_WAIT_2();
            __syncthreads();
            load_chunk(q + 3);

            const int k0 = (q & 7) * 32;
            const __half* Bs = Brg + st * BTILE_ELT;

#pragma unroll
            for (int kk = 0; kk < 2; kk++) {
                uint32_t afrag[4][4];
                uint32_t bfrag[4][2];
#pragma unroll
                for (int ni = 0; ni < 4; ni++) {
                    uint32_t addr = smem_u32(Bs + (b_row_sel + ni * 8) * BPITCH + kk * 16 + b_col_sel);
                    asm volatile("ldmatrix.sync.aligned.m8n8.x2.shared.b16 {%0,%1}, [%2];"
                        : "=r"(bfrag[ni][0]), "=r"(bfrag[ni][1])
                        : "r"(addr));
                }
#pragma unroll
                for (int mi = 0; mi < 4; mi++) {
                    uint32_t addr = smem_u32(At + (a_row_sel + mi * 16) * APITCH + k0 + kk * 16 + a_col_sel);
                    asm volatile("ldmatrix.sync.aligned.m8n8.x4.shared.b16 {%0,%1,%2,%3}, [%4];"
                        : "=r"(afrag[mi][0]), "=r"(afrag[mi][1]), "=r"(afrag[mi][2]), "=r"(afrag[mi][3])
                        : "r"(addr));
                }
#pragma unroll
                for (int mi = 0; mi < 4; mi++) {
#pragma unroll
                    for (int ni = 0; ni < 4; ni++) {
                        asm volatile(
                            "mma.sync.aligned.m16n8k16.row.col.f32.f16.f16.f32 "
                            "{%0,%1,%2,%3}, {%4,%5,%6,%7}, {%8,%9}, {%0,%1,%2,%3};"
                            : "+f"(acc[mi][ni][0]), "+f"(acc[mi][ni][1]),
                              "+f"(acc[mi][ni][2]), "+f"(acc[mi][ni][3])
                            : "r"(afrag[mi][0]), "r"(afrag[mi][1]), "r"(afrag[mi][2]), "r"(afrag[mi][3]),
                              "r"(bfrag[ni][0]), "r"(bfrag[ni][1]));
                    }
                }
            }

            // End of an n-block: epilogue (contiguous half2) + acc reset
            if ((q & 7) == 7) {
                const int nt    = bx * 3 + (q >> 3);
                const int w_idx = nt >> 2;
                const int nbase = (nt & 3) * 128;
                const int g  = lane >> 2;
                const int tg = lane & 3;

                const float* bsrc = (w_idx == 0) ? br : ((w_idx == 1) ? bz : nullptr);
                float2 bias[4];
#pragma unroll
                for (int ni = 0; ni < 4; ni++) {
                    int hh = nbase + warp_n * 32 + tg * 2 + ni * 8;
                    bias[ni] = bsrc ? *(const float2*)(bsrc + hh) : make_float2(0.f, 0.f);
                }

#pragma unroll
                for (int mi = 0; mi < 4; mi++) {
#pragma unroll
                    for (int rr = 0; rr < 2; rr++) {
                        int m  = m0 + warp_m * 64 + mi * 16 + g + rr * 8;
                        int bb = m >> 9;
                        int t  = m & 511;
                        __half* dst = g_scratch + (size_t)w_idx * TBH + (size_t)t * BH
                                    + (size_t)bb * HH + nbase + warp_n * 32 + tg * 2;
#pragma unroll
                        for (int ni = 0; ni < 4; ni++) {
                            float vx = (rr ? acc[mi][ni][2] : acc[mi][ni][0]) + bias[ni].x;
                            float vy = (rr ? acc[mi][ni][3] : acc[mi][ni][1]) + bias[ni].y;
                            *(__half2*)(dst + ni * 8) = __floats2half2_rn(vx, vy);
                        }
                    }
                }

#pragma unroll
                for (int i = 0; i < 4; i++)
#pragma unroll
                    for (int j = 0; j < 4; j++)
#pragma unroll
                        for (int qq = 0; qq < 4; qq++) acc[i][j][qq] = 0.0f;
            }
        }

        // Publish: all stores visible, then bump this m-tile's flag.
        __threadfence();
        __syncthreads();
        if (tid == 0) atomicAdd(&g_flags[my], 1);

    } else {
        // =================== Scan role ===================
        const int sid = bid - NGEMM;              // 0..255
        const int idx = sid * 256 + tid;          // 0..65535
        const int h = idx & (HH - 1);
        const int b = idx >> 9;                   // = sid >> 1 (constant per CTA)

        float state = h0[idx];
        const float mrv = mr[h];
        const float mzv = mz[h];

        const __half* pr = g_scratch + idx;
        const __half* pz = g_scratch + TBH + idx;
        const __half* ph = g_scratch + 2u * TBH + idx;

        float* o = out + (size_t)b * (TT * HH) + h;

        __half pa[PFD], pc[PFD], pd[PFD];

        for (int tb = 0; tb < 4; tb++) {
            // Wait for this 128-t block (+1 lookahead for the prefetch ring).
            if (tid == 0) {
                const int f0 = 4 * b + tb;
                const int f1 = 4 * b + ((tb < 3) ? tb + 1 : 3);
                while (((volatile int*)g_flags)[f0] < 4) __nanosleep(64);
                while (((volatile int*)g_flags)[f1] < 4) __nanosleep(64);
            }
            __syncthreads();
            __threadfence();   // acquire: order flag observation before data loads

            if (tb == 0) {
#pragma unroll
                for (int u = 0; u < PFD; u++) {
                    size_t off = (size_t)u * BH;
                    pa[u] = __ldg(pr + off);
                    pc[u] = __ldg(pz + off);
                    pd[u] = __ldg(ph + off);
                }
            }

            for (int ti = 0; ti < 128; ti += PFD) {
#pragma unroll
                for (int u = 0; u < PFD; u++) {
                    const int t = tb * 128 + ti + u;
                    float a0 = __half2float(pa[u]);
                    float c0 = __half2float(pc[u]);
                    float d0 = __half2float(pd[u]);

                    if (t + PFD < TT) {
                        size_t off = (size_t)(t + PFD) * BH;
                        pa[u] = __ldg(pr + off);
                        pc[u] = __ldg(pz + off);
                        pd[u] = __ldg(ph + off);
                    }

                    float r = htanh(fmaf(state, mrv, a0)) + 1.0f;
                    float z = fmaf(0.5f, htanh(0.5f * fmaf(state, mzv, c0)), 0.5f);
                    float inner = htanh(fmaf(r, state, d0));
                    state = fmaf(z, state - inner, inner);   // z*h + (1-z)*inner

                    __stcs(o + (size_t)t * HH, state);
                }
            }
        }
    }
}

// ---------------------------------------------------------------------------
// Launch
// ---------------------------------------------------------------------------
extern "C" void kernel_launch(void* const* d_in, const int* in_sizes, int n_in,
                              void* d_out, int out_size)
{
    const float* x  = (const float*)d_in[0];
    const float* h0 = (const float*)d_in[1];
    const float* wr = (const float*)d_in[2];
    const float* wz = (const float*)d_in[3];
    const float* wh = (const float*)d_in[4];
    const float* mr = (const float*)d_in[5];
    const float* mz = (const float*)d_in[6];
    const float* br = (const float*)d_in[7];
    const float* bz = (const float*)d_in[8];
    float* out = (float*)d_out;

    static int smem_set = 0;
    if (!smem_set) {
        cudaFuncSetAttribute(fused_kernel, cudaFuncAttributeMaxDynamicSharedMemorySize, GEMM_SMEM);
        smem_set = 1;
    }

    convert_w<<<(3 * DD * HH) / 256, 256>>>(wr, wz, wh);

    fused_kernel<<<NGEMM + NSCAN, 256, GEMM_SMEM>>>(x, br, bz, h0, mr, mz, out);
}